// round 5
// baseline (speedup 1.0000x reference)
#include <cuda_runtime.h>
#include <cstdint>

// out[n, :] = weight[idx_n, :] where one_hot[n, idx_n] == 1.0
// N = 8192, VOCAB = 8192, D = 1024, fp32.
//
// Persistent warp-per-row with atomic work stealing.
// Phase 1: scan the one-hot row 1024 floats per iteration (8x uint4 per lane,
//          streaming loads) with early exit via ballot.
// Phase 2: same warp copies the 4KB weight row (float4, coalesced).
// Counters self-reset (last block) so the kernel is graph-replay safe.

#define N_ROWS 8192
#define VOCAB  8192
#define DIM    1024
#define THREADS 256
#define GRID    592          // ~4 blocks/SM resident on 148 SMs

__device__ unsigned int g_work = 0;
__device__ unsigned int g_done = 0;

__global__ __launch_bounds__(THREADS) void onehot_gather_kernel(
    const float* __restrict__ one_hot,
    const float* __restrict__ weight,
    float* __restrict__ out)
{
    const int lane = threadIdx.x & 31;
    const unsigned FULL = 0xFFFFFFFFu;

    for (;;) {
        // --- grab next row (one atomic per warp) ---
        unsigned row_id;
        if (lane == 0) row_id = atomicAdd(&g_work, 1u);
        row_id = __shfl_sync(FULL, row_id, 0);
        if (row_id >= N_ROWS) break;

        const uint4* __restrict__ row =
            reinterpret_cast<const uint4*>(one_hot + (size_t)row_id * VOCAB);

        // --- phase 1: find the nonzero (8x uint4 per lane = 1024 floats/iter) ---
        int idx = -1;
        #pragma unroll 1
        for (int base = 0; base < VOCAB / 4; base += 256) {
            uint4 v[8];
            #pragma unroll
            for (int j = 0; j < 8; j++)
                v[j] = __ldcs(row + base + j * 32 + lane);

            unsigned nz = 0;
            #pragma unroll
            for (int j = 0; j < 8; j++)
                if ((v[j].x | v[j].y | v[j].z | v[j].w) != 0u)
                    nz |= 1u << j;

            unsigned m = __ballot_sync(FULL, nz != 0u);
            if (m) {
                int src = __ffs(m) - 1;
                int my_idx = -1;
                if (nz) {
                    int j = __ffs(nz) - 1;
                    uint4 w = v[j];
                    int e = (w.x != 0u) ? 0 : (w.y != 0u) ? 1 : (w.z != 0u) ? 2 : 3;
                    my_idx = (base + j * 32 + lane) * 4 + e;
                }
                idx = __shfl_sync(FULL, my_idx, src);
                break;
            }
        }

        float4* __restrict__ orow =
            reinterpret_cast<float4*>(out + (size_t)row_id * DIM);

        if (idx < 0) {
            // defensive: all-zero row -> zeros
            float4 z = make_float4(0.f, 0.f, 0.f, 0.f);
            #pragma unroll
            for (int i = 0; i < DIM / 4 / 32; i++)
                orow[i * 32 + lane] = z;
            continue;
        }

        // --- phase 2: copy weight[idx, :] (4KB) ---
        const float4* __restrict__ wrow =
            reinterpret_cast<const float4*>(weight + (size_t)idx * DIM);
        #pragma unroll
        for (int i = 0; i < DIM / 4 / 32; i++)   // 8 iterations
            orow[i * 32 + lane] = wrow[i * 32 + lane];
    }

    // --- epilogue: last block resets counters for the next graph replay ---
    __syncthreads();
    if (threadIdx.x == 0) {
        unsigned d = atomicAdd(&g_done, 1u);
        if (d == (unsigned)(gridDim.x - 1)) {
            g_work = 0;
            g_done = 0;
            __threadfence();
        }
    }
}

extern "C" void kernel_launch(void* const* d_in, const int* in_sizes, int n_in,
                              void* d_out, int out_size)
{
    const float* one_hot = (const float*)d_in[0];  // [N, VOCAB] fp32
    const float* weight  = (const float*)d_in[1];  // [VOCAB, D] fp32
    float* out = (float*)d_out;                    // [N, D] fp32

    onehot_gather_kernel<<<GRID, THREADS>>>(one_hot, weight, out);
}

// round 8
// speedup vs baseline: 1.1231x; 1.1231x over previous
#include <cuda_runtime.h>
#include <cstdint>

// out[n, :] = weight[idx_n, :] where one_hot[n, idx_n] == 1.0
// N = 8192, VOCAB = 8192, D = 1024, fp32.
//
// Warp-per-row, full grid (all 8192 warps resident in one wave).
// Phase 1: scan the one-hot row 1024 floats per iteration (8x uint4 per lane,
//          streaming loads), reducing each load to a 1-bit flag immediately
//          so registers stay low; early exit via ballot. On the (once-per-row)
//          hit, re-load the winning uint4 (L1/L2 hit) to find the element.
// Phase 2: same warp copies the 4KB weight row (float4, coalesced).

#define N_ROWS 8192
#define VOCAB  8192
#define DIM    1024
#define WARPS_PER_BLOCK 8
#define THREADS (WARPS_PER_BLOCK * 32)

__global__ __launch_bounds__(THREADS, 6) void onehot_gather_kernel(
    const float* __restrict__ one_hot,
    const float* __restrict__ weight,
    float* __restrict__ out)
{
    const int warp_global = (blockIdx.x * blockDim.x + threadIdx.x) >> 5;
    const int lane = threadIdx.x & 31;
    const unsigned FULL = 0xFFFFFFFFu;
    if (warp_global >= N_ROWS) return;

    const uint4* __restrict__ row =
        reinterpret_cast<const uint4*>(one_hot + (size_t)warp_global * VOCAB);

    // --- phase 1: find the nonzero. 8x uint4 per lane = 4KB per iteration,
    //     max 8 iterations (row = 32KB). ---
    int idx = -1;
    #pragma unroll 1
    for (int base = 0; base < VOCAB / 4; base += 256) {
        unsigned nz = 0;
        #pragma unroll
        for (int j = 0; j < 8; j++) {
            uint4 v = __ldcs(row + base + j * 32 + lane);
            if ((v.x | v.y | v.z | v.w) != 0u)
                nz |= 1u << j;
        }

        unsigned m = __ballot_sync(FULL, nz != 0u);
        if (m) {
            int src = __ffs(m) - 1;
            int my_idx = -1;
            if (nz) {
                int j = __ffs(nz) - 1;
                // rare path (once per row): re-load the winning chunk, L1/L2 hit
                uint4 w = row[base + j * 32 + lane];
                int e = (w.x != 0u) ? 0 : (w.y != 0u) ? 1 : (w.z != 0u) ? 2 : 3;
                my_idx = (base + j * 32 + lane) * 4 + e;
            }
            idx = __shfl_sync(FULL, my_idx, src);
            break;
        }
    }

    float4* __restrict__ orow =
        reinterpret_cast<float4*>(out + (size_t)warp_global * DIM);

    if (idx < 0) {
        // defensive: all-zero row -> zeros
        float4 z = make_float4(0.f, 0.f, 0.f, 0.f);
        #pragma unroll
        for (int i = 0; i < DIM / 4 / 32; i++)
            orow[i * 32 + lane] = z;
        return;
    }

    // --- phase 2: copy weight[idx, :] (4KB, coalesced) ---
    const float4* __restrict__ wrow =
        reinterpret_cast<const float4*>(weight + (size_t)idx * DIM);
    #pragma unroll
    for (int i = 0; i < DIM / 4 / 32; i++)   // 8 iterations
        orow[i * 32 + lane] = wrow[i * 32 + lane];
}

extern "C" void kernel_launch(void* const* d_in, const int* in_sizes, int n_in,
                              void* d_out, int out_size)
{
    const float* one_hot = (const float*)d_in[0];  // [N, VOCAB] fp32
    const float* weight  = (const float*)d_in[1];  // [VOCAB, D] fp32
    float* out = (float*)d_out;                    // [N, D] fp32

    const int blocks = N_ROWS / WARPS_PER_BLOCK;   // 1024
    onehot_gather_kernel<<<blocks, THREADS>>>(one_hot, weight, out);
}